// round 9
// baseline (speedup 1.0000x reference)
#include <cuda_runtime.h>
#include <cuda_fp16.h>
#include <cstdint>

typedef unsigned short u16;
typedef unsigned int   u32;

constexpr int STR = 72;   // smem row stride in halves (conflict-free for ldsm)

// ─── helpers ───────────────────────────────────────────────────────────────
__device__ __forceinline__ u32 smem_u32(const void* p){
    u32 a;
    asm("{ .reg .u64 t; cvta.to.shared.u64 t, %1; cvt.u32.u64 %0, t; }"
        : "=r"(a) : "l"(p));
    return a;
}
__device__ __forceinline__ void ldsm4(u32 addr, u32& r0, u32& r1, u32& r2, u32& r3){
    asm volatile("ldmatrix.sync.aligned.m8n8.x4.shared.b16 {%0,%1,%2,%3}, [%4];"
        : "=r"(r0), "=r"(r1), "=r"(r2), "=r"(r3) : "r"(addr));
}
__device__ __forceinline__ void mma_(float* c, const u32* a, u32 b0, u32 b1){
    asm volatile("mma.sync.aligned.m16n8k16.row.col.f32.f16.f16.f32 "
        "{%0,%1,%2,%3},{%4,%5,%6,%7},{%8,%9},{%0,%1,%2,%3};"
        : "+f"(c[0]), "+f"(c[1]), "+f"(c[2]), "+f"(c[3])
        : "r"(a[0]), "r"(a[1]), "r"(a[2]), "r"(a[3]), "r"(b0), "r"(b1));
}
#define CPA16(dst, src) \
    asm volatile("cp.async.cg.shared.global [%0], [%1], 16;" :: "r"(dst), "l"(src))
#define CPA_COMMIT()  asm volatile("cp.async.commit_group;" ::: "memory")
#define CPA_WAIT0()   asm volatile("cp.async.wait_group 0;" ::: "memory")
#define CPA_WAIT_G1() asm volatile("cp.async.wait_group 1;" ::: "memory")
#define CPA_WAIT() do { CPA_COMMIT(); CPA_WAIT0(); } while(0)

__device__ __forceinline__ void sp2(float a, float b, u32& H, u32& L){
    __half2 h = __floats2half2_rn(a, b);
    float2 hf = __half22float2(h);
    __half2 l = __floats2half2_rn(a - hf.x, b - hf.y);
    H = *(u32*)&h; L = *(u32*)&l;
}
__device__ __forceinline__ float2 dec(u32 v){
    __half2 h = *(__half2*)&v; return __half22float2(h);
}
__device__ __forceinline__ float hswish(float x){
    return x * __saturatef((x + 3.0f) * (1.0f / 6.0f));
}

// fragment loads: A = 8 regs (hi 4 + lo 4), B = 16 regs (hi 8 + lo 8)
__device__ __forceinline__ void ldA8(u32* A, u32 aH, u32 aL, int kc){
    ldsm4(aH + kc*32, A[0], A[1], A[2], A[3]);
    ldsm4(aL + kc*32, A[4], A[5], A[6], A[7]);
}
__device__ __forceinline__ void ldB16(u32* B, u32 bH, u32 bL, int kc, int jbp){
    const u32 off = kc*32 + jbp*32*STR*2;
    ldsm4(bH + off,            B[0],  B[1],  B[2],  B[3]);
    ldsm4(bH + off + 16*STR*2, B[4],  B[5],  B[6],  B[7]);
    ldsm4(bL + off,            B[8],  B[9],  B[10], B[11]);
    ldsm4(bL + off + 16*STR*2, B[12], B[13], B[14], B[15]);
}
// 12 MMAs of one chunk: acc groups base..base+3, passes hi*hi, lo*hi, hi*lo
__device__ __forceinline__ void mma12(float acc[8][4], int base, const u32* A, const u32* B){
    float* a0 = acc[base+0]; float* a1 = acc[base+1];
    float* a2 = acc[base+2]; float* a3 = acc[base+3];
    mma_(a0, A,   B[0], B[1]);  mma_(a1, A,   B[2], B[3]);
    mma_(a2, A,   B[4], B[5]);  mma_(a3, A,   B[6], B[7]);
    mma_(a0, A+4, B[0], B[1]);  mma_(a1, A+4, B[2], B[3]);
    mma_(a2, A+4, B[4], B[5]);  mma_(a3, A+4, B[6], B[7]);
    mma_(a0, A,   B[8], B[9]);  mma_(a1, A,   B[10], B[11]);
    mma_(a2, A,   B[12], B[13]); mma_(a3, A,  B[14], B[15]);
}
// pipelined 4kc x 2jbp block: chunk i+1 fragment loads issued before chunk i MMAs
__device__ __forceinline__ void gemm_block(float acc[8][4], u32 aH, u32 aL, u32 bH, u32 bL,
                                           u32 Ab[2][8], u32 Bb[2][16]){
    ldA8(Ab[0], aH, aL, 0);
    ldB16(Bb[0], bH, bL, 0, 0);
    #pragma unroll
    for (int ch = 0; ch < 8; ch++) {
        const int kc = ch >> 1, jbp = ch & 1;
        if (ch < 7) {
            const int nkc = (ch + 1) >> 1, njb = (ch + 1) & 1;
            if (njb == 0) ldA8(Ab[nkc & 1], aH, aL, nkc);
            ldB16(Bb[(ch + 1) & 1], bH, bL, nkc, njb);
        }
        mma12(acc, 4*jbp, Ab[kc & 1], Bb[ch & 1]);
    }
}

// ─── global scratch ────────────────────────────────────────────────────────
#define PXT 409600
#define TPAD (16*162*162)
#define WTOT 118784

__device__ __align__(16) u16 g_yh[PXT*64], g_yl[PXT*64];
__device__ __align__(16) u16 g_ah[PXT*64], g_al[PXT*64];
__device__ __align__(16) u16 g_bh[PXT*64], g_bl[PXT*64];
__device__ __align__(16) u16 g_th[TPAD*64], g_tl[TPAD*64];
__device__ __align__(16) u16 g_wh[WTOT], g_wl[WTOT];
__device__ float g_sb[1280];

#define WO_CV1   0
#define WO_M0A   8192
#define WO_M0B   12288
#define WO_M1A   49152
#define WO_M1B   53248
#define WO_CV3   90112
#define WO_CV2P  94208
#define WO_CV4   102400

#define SB_CV1   0
#define SB_M0A   128
#define SB_M0B   256
#define SB_M1A   384
#define SB_M1B   512
#define SB_CATA  640
#define SB_CATB  768
#define SB_CV4   896

// ─── single fused prep kernel ──────────────────────────────────────────────
__global__ void prep_all(
    const float* cv1w, const float* m0a, const float* m0b,
    const float* m1a,  const float* m1b, const float* cv3,
    const float* cv2p, const float* cv4,
    const float* c1bn, const float* a0bn, const float* b0bn,
    const float* a1bn, const float* b1bn, const float* catbn, const float* c4bn,
    u16* wh, u16* wl, float* sb, u16* th, u16* tl)
{
    const int bid = blockIdx.x, tid = threadIdx.x;
    if (bid < 29) {
        const float* src; u16 *dh, *dl; int CIN = 64, COUT = 64, b0;
        if      (bid < 2)  { src = cv1w; dh = wh+WO_CV1;  dl = wl+WO_CV1;  CIN = 128; b0 = 0; }
        else if (bid < 3)  { src = m0a;  dh = wh+WO_M0A;  dl = wl+WO_M0A;  b0 = 2; }
        else if (bid < 12) { src = m0b;  dh = wh+WO_M0B;  dl = wl+WO_M0B;  b0 = 3; }
        else if (bid < 13) { src = m1a;  dh = wh+WO_M1A;  dl = wl+WO_M1A;  b0 = 12; }
        else if (bid < 22) { src = m1b;  dh = wh+WO_M1B;  dl = wl+WO_M1B;  b0 = 13; }
        else if (bid < 23) { src = cv3;  dh = wh+WO_CV3;  dl = wl+WO_CV3;  b0 = 22; }
        else if (bid < 25) { src = cv2p; dh = wh+WO_CV2P; dl = wl+WO_CV2P; CIN = 128; b0 = 23; }
        else               { src = cv4;  dh = wh+WO_CV4;  dl = wl+WO_CV4;  CIN = 128; COUT = 128; b0 = 25; }
        const int base = (bid - b0) * 4096;
        const int per = CIN * COUT;
        #pragma unroll 4
        for (int j = 0; j < 16; j++) {
            int e = base + tid + j * 256;
            int tap = e / per, r = e - tap * per;
            int ci = r / COUT, co = r - ci * COUT;
            float w = src[e];
            __half h = __float2half_rn(w);
            __half l = __float2half_rn(w - __half2float(h));
            int d = tap * per + co * CIN + ci;
            dh[d] = *(u16*)&h; dl[d] = *(u16*)&l;
        }
    } else if (bid == 29) {
        auto seg = [&](int off, const float* s, int C, int stride, int choff){
            for (int c = tid; c < C; c += 256) {
                float g = s[choff + c], b = s[stride + choff + c];
                float m = s[2*stride + choff + c], v = s[3*stride + choff + c];
                float sc = g * rsqrtf(v + 1e-3f);
                sb[off + c] = sc; sb[off + C + c] = b - m * sc;
            }
        };
        seg(SB_CV1,  c1bn, 64, 64, 0);
        seg(SB_M0A,  a0bn, 64, 64, 0);
        seg(SB_M0B,  b0bn, 64, 64, 0);
        seg(SB_M1A,  a1bn, 64, 64, 0);
        seg(SB_M1B,  b1bn, 64, 64, 0);
        seg(SB_CATA, catbn, 64, 128, 0);
        seg(SB_CATB, catbn, 64, 128, 64);
        seg(SB_CV4,       c4bn, 64, 128, 0);
        seg(SB_CV4 + 128, c4bn, 64, 128, 64);
    } else {
        int i = (bid - 30) * 256 + tid;
        if (i >= 16 * 644) return;
        int img = i / 644, r = i - img * 644;
        int y, x;
        if      (r < 162) { y = 0;   x = r; }
        else if (r < 324) { y = 161; x = r - 162; }
        else if (r < 484) { x = 0;   y = r - 324 + 1; }
        else              { x = 161; y = r - 484 + 1; }
        long long q = (((long long)img * 162 + y) * 162 + x) * 64;
        uint4 z = make_uint4(0,0,0,0);
        #pragma unroll
        for (int c = 0; c < 8; c++) { *(uint4*)(th + q + c*8) = z; *(uint4*)(tl + q + c*8) = z; }
    }
}

// ─── 1x1 conv GEMM (HMMA): persistent CTAs, pipelined A, W preloaded ───────
template<int CIN, int SRC, int OUTM, int ACT>
__global__ void __launch_bounds__(256, 2) g1x1(
    const float* __restrict__ xf,
    const u16* __restrict__ pah, const u16* __restrict__ pal,
    const u16* __restrict__ pbh, const u16* __restrict__ pbl,
    const u16* __restrict__ wh,  const u16* __restrict__ wl,
    const float* __restrict__ sb,
    u16* __restrict__ oh, u16* __restrict__ ol, float* __restrict__ of,
    int ntiles)
{
    constexpr int KB  = CIN / 64;
    constexpr int APL = 128 * STR * 2;   // 18432 per plane
    constexpr int WPL = 64 * STR * 2;    // 9216  per plane

    extern __shared__ char sm[];
    float* sbs  = (float*)sm;
    char* Wbase = sm + 512;                  // [kb][hi|lo]
    char* Abase = Wbase + KB * 2 * WPL;      // [buf][hi|lo]

    const int tid = threadIdx.x;
    const int cy  = blockIdx.y;
    const u16* whp = wh + cy * 64 * CIN;
    const u16* wlp = wl + cy * 64 * CIN;

    for (int c = tid; c < 128; c += 256) sbs[c] = sb[cy * 128 + c];

    const u32 WA = smem_u32(Wbase), AA = smem_u32(Abase);

    #pragma unroll
    for (int kb = 0; kb < KB; kb++)
        for (int i = tid; i < 512; i += 256) {
            int n = i >> 3, c8 = i & 7;
            u32 off = kb * 2 * WPL + (n * STR + c8 * 8) * 2;
            CPA16(WA + off,       whp + n * CIN + kb * 64 + c8 * 8);
            CPA16(WA + off + WPL, wlp + n * CIN + kb * 64 + c8 * 8);
        }

    auto stageA = [&](int t, int kb, int buf){
        long long p0 = (long long)t * 128;
        const u32 AH = AA + buf * 2 * APL;
        char* AB = Abase + buf * 2 * APL;
        for (int i = tid; i < 1024; i += 256) {
            int row = i >> 3, c8 = i & 7;
            u32 off = (row * STR + c8 * 8) * 2;
            if (SRC == 0) {
                const float* g = xf + (p0 + row) * CIN + kb * 64 + c8 * 8;
                float4 f1 = *(const float4*)g, f2 = *(const float4*)(g + 4);
                uint4 H, L;
                sp2(f1.x, f1.y, H.x, L.x); sp2(f1.z, f1.w, H.y, L.y);
                sp2(f2.x, f2.y, H.z, L.z); sp2(f2.z, f2.w, H.w, L.w);
                *(uint4*)(AB + off) = H; *(uint4*)(AB + APL + off) = L;
            } else if (SRC == 1) {
                CPA16(AH + off,       pah + (p0 + row) * CIN + kb * 64 + c8 * 8);
                CPA16(AH + APL + off, pal + (p0 + row) * CIN + kb * 64 + c8 * 8);
            } else {
                const u16* shp = kb ? pbh : pah;
                const u16* slp = kb ? pbl : pal;
                long long so = (p0 + row) * 64 + c8 * 8;
                CPA16(AH + off,       shp + so);
                CPA16(AH + APL + off, slp + so);
            }
        }
    };

    const int warp = tid >> 5, lane = tid & 31;
    const int arow  = 16 * warp + (lane & 7) + ((lane & 8) ? 8 : 0);
    const int akoff = (lane & 16) ? 8 : 0;
    const u32 aOff = (arow * STR + akoff) * 2;
    const int brow  = (lane & 7) + ((lane & 16) ? 8 : 0);
    const int bkoff = (lane & 8) ? 8 : 0;
    const u32 bOff = (brow * STR + bkoff) * 2;

    const int gr = lane >> 2, c2l = (lane & 3) * 2;
    const int coff = cy * 64;

    const int t0 = blockIdx.x;
    if (t0 < ntiles) stageA(t0, 0, 0);
    CPA_COMMIT();

    int buf = 0;
    float acc[8][4];
    u32 Ab[2][8], Bb[2][16];

    for (int t = t0; t < ntiles; t += gridDim.x) {
        #pragma unroll
        for (int n = 0; n < 8; n++)
            #pragma unroll
            for (int j = 0; j < 4; j++) acc[n][j] = 0.f;

        #pragma unroll
        for (int kb = 0; kb < KB; kb++) {
            int nt = t, nkb = kb + 1;
            if (nkb == KB) { nkb = 0; nt = t + gridDim.x; }
            const bool hn = (nt < ntiles);
            if (hn) stageA(nt, nkb, buf ^ 1);
            CPA_COMMIT();
            if (hn) { CPA_WAIT_G1(); } else { CPA_WAIT0(); }
            __syncthreads();

            const u32 aH = AA + buf * 2 * APL + aOff;
            const u32 aL = aH + APL;
            const u32 bH = WA + kb * 2 * WPL + bOff;
            const u32 bL = bH + WPL;

            gemm_block(acc, aH, aL, bH, bL, Ab, Bb);

            if (kb == KB - 1) {
                #pragma unroll
                for (int rs = 0; rs < 2; rs++) {
                    int row = 16*warp + 8*rs + gr;
                    long long p = (long long)t * 128 + row;
                    long long q = 0;
                    if (OUTM == 0) q = p * 64;
                    else if (OUTM == 1) {
                        int pi = (int)p;
                        int img = pi / 25600, r = pi - img * 25600;
                        int y = r / 160, x = r - y * 160;
                        q = (((long long)img * 162 + y + 1) * 162 + (x + 1)) * 64;
                    }
                    #pragma unroll
                    for (int nb = 0; nb < 8; nb++) {
                        float v0 = sbs[8*nb + c2l]     * acc[nb][2*rs]     + sbs[64 + 8*nb + c2l];
                        float v1 = sbs[8*nb + c2l + 1] * acc[nb][2*rs + 1] + sbs[64 + 8*nb + c2l + 1];
                        if (ACT == 0) { v0 = hswish(v0); v1 = hswish(v1); }
                        else { v0 = v0 >= 0.f ? v0 : 0.1f*v0; v1 = v1 >= 0.f ? v1 : 0.1f*v1; }
                        if (OUTM == 2) {
                            *(float2*)(of + p * 128 + coff + 8*nb + c2l) = make_float2(v0, v1);
                        } else {
                            u32 H, L; sp2(v0, v1, H, L);
                            *(u32*)(oh + q + 8*nb + c2l) = H;
                            *(u32*)(ol + q + 8*nb + c2l) = L;
                        }
                    }
                }
            }
            __syncthreads();
            buf ^= 1;
        }
    }
}

// ─── 3x3 conv: persistent CTAs, ALL 9 weight taps resident in smem ─────────
// 1 CTA/SM. Per tile: halo load -> barrier -> 9-tap MMA stream (NO barriers)
// -> epilogue (BN+hswish+residual RMW) -> barrier.
__global__ void __launch_bounds__(256, 1) c3x3(
    const u16* __restrict__ th, const u16* __restrict__ tl,
    const u16* __restrict__ wh, const u16* __restrict__ wl,
    const float* __restrict__ sb,
    u16* __restrict__ yh, u16* __restrict__ yl, int ntiles)
{
    constexpr int APL = 180 * STR * 2;   // 25920 per halo plane
    constexpr int WPL = 64 * STR * 2;    // 9216  per weight plane

    extern __shared__ char sm[];
    float* sbs = (float*)sm;
    char* Wall = sm + 512;               // [tap][hi|lo] : 9*2*WPL = 165888
    char* Ah   = Wall + 9 * 2 * WPL;
    char* Al   = Ah + APL;               // total 512+165888+51840 = 218240

    const int tid = threadIdx.x;
    for (int c = tid; c < 128; c += 256) sbs[c] = sb[c];

    const u32 WA = smem_u32(Wall), AhA = smem_u32(Ah), AlA = smem_u32(Al);

    // load ALL 9 weight taps, both planes, ONCE per CTA
    for (int i = tid; i < 4608; i += 256) {
        int tap = i >> 9, r = i & 511;
        int n = r >> 3, c8 = r & 7;
        u32 off = tap * 2 * WPL + (n * STR + c8 * 8) * 2;
        CPA16(WA + off,       wh + tap*4096 + n*64 + c8*8);
        CPA16(WA + off + WPL, wl + tap*4096 + n*64 + c8*8);
    }
    CPA_COMMIT();

    const int warp = tid >> 5, lane = tid & 31;
    const int acol  = lane & 15;
    const int akoff = (lane & 16) ? 8 : 0;
    const int brow  = (lane & 7) + ((lane & 16) ? 8 : 0);
    const int bkoff = (lane & 8) ? 8 : 0;
    const u32 bOff = (brow * STR + bkoff) * 2;
    const int gr = lane >> 2, c2l = (lane & 3) * 2;

    float acc[8][4];
    u32 Ab[2][8], Bb[2][16];

    for (int t = blockIdx.x; t < ntiles; t += gridDim.x) {
        const int img = t / 200, tt = t - img * 200;
        const int ty = tt / 10, tx = tt - ty * 10;
        const int y0 = ty * 8, x0 = tx * 16;

        // halo 10x18 rows x 64ch, both planes (padded input: no predicates)
        for (int i = tid; i < 1440; i += 256) {
            int hr = i >> 3, c8 = i & 7;
            int hy = hr / 18, hx = hr - hy * 18;
            long long s = (((long long)img * 162 + y0 + hy) * 162 + (x0 + hx)) * 64 + c8 * 8;
            u32 off = (hr * STR + c8 * 8) * 2;
            CPA16(AhA + off, th + s);
            CPA16(AlA + off, tl + s);
        }
        CPA_WAIT();              // drains halo (and W on first tile)
        __syncthreads();

        #pragma unroll
        for (int n = 0; n < 8; n++)
            #pragma unroll
            for (int j = 0; j < 4; j++) acc[n][j] = 0.f;

        for (int tap = 0; tap < 9; tap++) {     // rolled: small I$ footprint
            const int kh = tap / 3, kw = tap - kh * 3;
            const int hr = (warp + kh) * 18 + acol + kw;
            const u32 aH = AhA + (hr * STR + akoff) * 2;
            const u32 aL = AlA + (hr * STR + akoff) * 2;
            const u32 bH = WA + tap * 2 * WPL + bOff;
            const u32 bL = bH + WPL;
            gemm_block(acc, aH, aL, bH, bL, Ab, Bb);
        }

        // epilogue: BN + hswish + residual RMW into y planes
        #pragma unroll
        for (int rs = 0; rs < 2; rs++) {
            int xx = 8*rs + gr;
            long long q = ((long long)img * 25600 + (y0 + warp) * 160 + (x0 + xx)) * 64;
            #pragma unroll
            for (int nb = 0; nb < 8; nb++) {
                float2 yv0 = dec(*(const u32*)(yh + q + 8*nb + c2l));
                float2 yv1 = dec(*(const u32*)(yl + q + 8*nb + c2l));
                float v0 = sbs[8*nb + c2l]     * acc[nb][2*rs]     + sbs[64 + 8*nb + c2l];
                float v1 = sbs[8*nb + c2l + 1] * acc[nb][2*rs + 1] + sbs[64 + 8*nb + c2l + 1];
                v0 = hswish(v0) + yv0.x + yv1.x;
                v1 = hswish(v1) + yv0.y + yv1.y;
                u32 H, L; sp2(v0, v1, H, L);
                *(u32*)(yh + q + 8*nb + c2l) = H;
                *(u32*)(yl + q + 8*nb + c2l) = L;
            }
        }
        __syncthreads();   // all warps done reading halo before next overwrite
    }
}

// ─── host ──────────────────────────────────────────────────────────────────
extern "C" void kernel_launch(void* const* d_in, const int* in_sizes, int n_in,
                              void* d_out, int out_size)
{
    (void)in_sizes; (void)n_in; (void)out_size;
    const float* x         = (const float*)d_in[0];
    const float* cv1_w     = (const float*)d_in[1];
    const float* cv1_bn    = (const float*)d_in[2];
    const float* m0_cv1_w  = (const float*)d_in[3];
    const float* m0_cv1_bn = (const float*)d_in[4];
    const float* m0_cv2_w  = (const float*)d_in[5];
    const float* m0_cv2_bn = (const float*)d_in[6];
    const float* m1_cv1_w  = (const float*)d_in[7];
    const float* m1_cv1_bn = (const float*)d_in[8];
    const float* m1_cv2_w  = (const float*)d_in[9];
    const float* m1_cv2_bn = (const float*)d_in[10];
    const float* cv3_w     = (const float*)d_in[11];
    const float* cv2p_w    = (const float*)d_in[12];
    const float* bn_cat    = (const float*)d_in[13];
    const float* cv4_w     = (const float*)d_in[14];
    const float* cv4_bn    = (const float*)d_in[15];
    float* out = (float*)d_out;

    u16 *yh, *yl, *ah, *al, *bh, *bl, *th, *tl, *wh, *wl;
    float* sb;
    cudaGetSymbolAddress((void**)&yh, g_yh); cudaGetSymbolAddress((void**)&yl, g_yl);
    cudaGetSymbolAddress((void**)&ah, g_ah); cudaGetSymbolAddress((void**)&al, g_al);
    cudaGetSymbolAddress((void**)&bh, g_bh); cudaGetSymbolAddress((void**)&bl, g_bl);
    cudaGetSymbolAddress((void**)&th, g_th); cudaGetSymbolAddress((void**)&tl, g_tl);
    cudaGetSymbolAddress((void**)&wh, g_wh); cudaGetSymbolAddress((void**)&wl, g_wl);
    cudaGetSymbolAddress((void**)&sb, g_sb);

    constexpr int S1_64  = 512 + 1*2*9216 + 2*2*18432;     // 92672
    constexpr int S1_128 = 512 + 2*2*9216 + 2*2*18432;     // 111104
    constexpr int S3     = 512 + 9*2*9216 + 2*25920;       // 218240
    constexpr int NT = 3200;
    constexpr int GP = 304;     // g1x1: 2 CTAs x 152 SMs
    constexpr int GC = 152;     // c3x3: 1 CTA x 152 SMs (persistent, W resident)

    cudaFuncSetAttribute(g1x1<128,0,0,0>, cudaFuncAttributeMaxDynamicSharedMemorySize, S1_128);
    cudaFuncSetAttribute(g1x1< 64,1,1,0>, cudaFuncAttributeMaxDynamicSharedMemorySize, S1_64);
    cudaFuncSetAttribute(g1x1< 64,1,0,1>, cudaFuncAttributeMaxDynamicSharedMemorySize, S1_64);
    cudaFuncSetAttribute(g1x1<128,0,0,1>, cudaFuncAttributeMaxDynamicSharedMemorySize, S1_128);
    cudaFuncSetAttribute(g1x1<128,2,2,0>, cudaFuncAttributeMaxDynamicSharedMemorySize, S1_128);
    cudaFuncSetAttribute(c3x3,            cudaFuncAttributeMaxDynamicSharedMemorySize, S3);

    prep_all<<<71, 256>>>(cv1_w, m0_cv1_w, m0_cv2_w, m1_cv1_w, m1_cv2_w,
                          cv3_w, cv2p_w, cv4_w,
                          cv1_bn, m0_cv1_bn, m0_cv2_bn, m1_cv1_bn, m1_cv2_bn,
                          bn_cat, cv4_bn, wh, wl, sb, th, tl);

    g1x1<128,0,0,0><<<GP,256,S1_128>>>(x, 0,0,0,0, wh+WO_CV1, wl+WO_CV1, sb+SB_CV1, yh, yl, 0, NT);
    g1x1<64,1,1,0><<<GP,256,S1_64>>>(0, yh,yl,0,0, wh+WO_M0A, wl+WO_M0A, sb+SB_M0A, th, tl, 0, NT);
    c3x3<<<GC,256,S3>>>(th, tl, wh+WO_M0B, wl+WO_M0B, sb+SB_M0B, yh, yl, NT);
    g1x1<64,1,1,0><<<GP,256,S1_64>>>(0, yh,yl,0,0, wh+WO_M1A, wl+WO_M1A, sb+SB_M1A, th, tl, 0, NT);
    c3x3<<<GC,256,S3>>>(th, tl, wh+WO_M1B, wl+WO_M1B, sb+SB_M1B, yh, yl, NT);
    g1x1<64,1,0,1><<<GP,256,S1_64>>>(0, yh,yl,0,0, wh+WO_CV3, wl+WO_CV3, sb+SB_CATA, ah, al, 0, NT);
    g1x1<128,0,0,1><<<GP,256,S1_128>>>(x, 0,0,0,0, wh+WO_CV2P, wl+WO_CV2P, sb+SB_CATB, bh, bl, 0, NT);
    g1x1<128,2,2,0><<<dim3(GP,2),256,S1_128>>>(0, ah,al, bh,bl, wh+WO_CV4, wl+WO_CV4, sb+SB_CV4, 0, 0, out, NT);
}

// round 10
// speedup vs baseline: 1.3006x; 1.3006x over previous
#include <cuda_runtime.h>
#include <cuda_fp16.h>
#include <cstdint>

typedef unsigned short u16;
typedef unsigned int   u32;

constexpr int STR = 72;   // smem row stride in halves (conflict-free for ldsm)

// ─── helpers ───────────────────────────────────────────────────────────────
__device__ __forceinline__ u32 smem_u32(const void* p){
    u32 a;
    asm("{ .reg .u64 t; cvta.to.shared.u64 t, %1; cvt.u32.u64 %0, t; }"
        : "=r"(a) : "l"(p));
    return a;
}
__device__ __forceinline__ void ldsm4(u32 addr, u32& r0, u32& r1, u32& r2, u32& r3){
    asm volatile("ldmatrix.sync.aligned.m8n8.x4.shared.b16 {%0,%1,%2,%3}, [%4];"
        : "=r"(r0), "=r"(r1), "=r"(r2), "=r"(r3) : "r"(addr));
}
__device__ __forceinline__ void mma_(float* c, const u32* a, u32 b0, u32 b1){
    asm volatile("mma.sync.aligned.m16n8k16.row.col.f32.f16.f16.f32 "
        "{%0,%1,%2,%3},{%4,%5,%6,%7},{%8,%9},{%0,%1,%2,%3};"
        : "+f"(c[0]), "+f"(c[1]), "+f"(c[2]), "+f"(c[3])
        : "r"(a[0]), "r"(a[1]), "r"(a[2]), "r"(a[3]), "r"(b0), "r"(b1));
}
// fp16-accumulate variant for low-order correction terms
__device__ __forceinline__ void mma_h(u32* c, const u32* a, u32 b0, u32 b1){
    asm volatile("mma.sync.aligned.m16n8k16.row.col.f16.f16.f16.f16 "
        "{%0,%1},{%2,%3,%4,%5},{%6,%7},{%0,%1};"
        : "+r"(c[0]), "+r"(c[1])
        : "r"(a[0]), "r"(a[1]), "r"(a[2]), "r"(a[3]), "r"(b0), "r"(b1));
}
#define CPA16(dst, src) \
    asm volatile("cp.async.cg.shared.global [%0], [%1], 16;" :: "r"(dst), "l"(src))
#define CPA_COMMIT()  asm volatile("cp.async.commit_group;" ::: "memory")
#define CPA_WAIT0()   asm volatile("cp.async.wait_group 0;" ::: "memory")
#define CPA_WAIT_G1() asm volatile("cp.async.wait_group 1;" ::: "memory")
#define CPA_WAIT() do { CPA_COMMIT(); CPA_WAIT0(); } while(0)

__device__ __forceinline__ void sp2(float a, float b, u32& H, u32& L){
    __half2 h = __floats2half2_rn(a, b);
    float2 hf = __half22float2(h);
    __half2 l = __floats2half2_rn(a - hf.x, b - hf.y);
    H = *(u32*)&h; L = *(u32*)&l;
}
__device__ __forceinline__ float2 dec(u32 v){
    __half2 h = *(__half2*)&v; return __half22float2(h);
}
__device__ __forceinline__ float hswish(float x){
    return x * __saturatef((x + 3.0f) * (1.0f / 6.0f));
}

// fragment loads: A = 8 regs (hi 4 + lo 4), B = 16 regs (hi 8 + lo 8)
__device__ __forceinline__ void ldA8(u32* A, u32 aH, u32 aL, int kc){
    ldsm4(aH + kc*32, A[0], A[1], A[2], A[3]);
    ldsm4(aL + kc*32, A[4], A[5], A[6], A[7]);
}
__device__ __forceinline__ void ldB16(u32* B, u32 bH, u32 bL, int kc, int jbp){
    const u32 off = kc*32 + jbp*32*STR*2;
    ldsm4(bH + off,            B[0],  B[1],  B[2],  B[3]);
    ldsm4(bH + off + 16*STR*2, B[4],  B[5],  B[6],  B[7]);
    ldsm4(bL + off,            B[8],  B[9],  B[10], B[11]);
    ldsm4(bL + off + 16*STR*2, B[12], B[13], B[14], B[15]);
}
// 12 MMAs of one chunk: 4 fp32-acc (hi*hi) + 8 fp16-acc (lo*hi, hi*lo)
__device__ __forceinline__ void mma12(float accF[8][4], u32 accH[8][2], int base,
                                      const u32* A, const u32* B){
    #pragma unroll
    for (int g = 0; g < 4; g++)
        mma_(accF[base+g], A, B[2*g], B[2*g+1]);
    #pragma unroll
    for (int g = 0; g < 4; g++)
        mma_h(accH[base+g], A+4, B[2*g], B[2*g+1]);
    #pragma unroll
    for (int g = 0; g < 4; g++)
        mma_h(accH[base+g], A, B[8+2*g], B[8+2*g+1]);
}
// pipelined 4kc x 2jbp block: chunk i+1 fragment loads issued before chunk i MMAs
__device__ __forceinline__ void gemm_block(float accF[8][4], u32 accH[8][2],
                                           u32 aH, u32 aL, u32 bH, u32 bL,
                                           u32 Ab[2][8], u32 Bb[2][16]){
    ldA8(Ab[0], aH, aL, 0);
    ldB16(Bb[0], bH, bL, 0, 0);
    #pragma unroll
    for (int ch = 0; ch < 8; ch++) {
        const int kc = ch >> 1, jbp = ch & 1;
        if (ch < 7) {
            const int nkc = (ch + 1) >> 1, njb = (ch + 1) & 1;
            if (njb == 0) ldA8(Ab[nkc & 1], aH, aL, nkc);
            ldB16(Bb[(ch + 1) & 1], bH, bL, nkc, njb);
        }
        mma12(accF, accH, 4*jbp, Ab[kc & 1], Bb[ch & 1]);
    }
}

// ─── global scratch ────────────────────────────────────────────────────────
#define PXT 409600
#define TPAD (16*162*162)
#define WTOT 118784

__device__ __align__(16) u16 g_yh[PXT*64], g_yl[PXT*64];
__device__ __align__(16) u16 g_ah[PXT*64], g_al[PXT*64];
__device__ __align__(16) u16 g_bh[PXT*64], g_bl[PXT*64];
__device__ __align__(16) u16 g_th[TPAD*64], g_tl[TPAD*64];
__device__ __align__(16) u16 g_wh[WTOT], g_wl[WTOT];
__device__ float g_sb[1280];

#define WO_CV1   0
#define WO_M0A   8192
#define WO_M0B   12288
#define WO_M1A   49152
#define WO_M1B   53248
#define WO_CV3   90112
#define WO_CV2P  94208
#define WO_CV4   102400

#define SB_CV1   0
#define SB_M0A   128
#define SB_M0B   256
#define SB_M1A   384
#define SB_M1B   512
#define SB_CATA  640
#define SB_CATB  768
#define SB_CV4   896

// ─── single fused prep kernel ──────────────────────────────────────────────
__global__ void prep_all(
    const float* cv1w, const float* m0a, const float* m0b,
    const float* m1a,  const float* m1b, const float* cv3,
    const float* cv2p, const float* cv4,
    const float* c1bn, const float* a0bn, const float* b0bn,
    const float* a1bn, const float* b1bn, const float* catbn, const float* c4bn,
    u16* wh, u16* wl, float* sb, u16* th, u16* tl)
{
    const int bid = blockIdx.x, tid = threadIdx.x;
    if (bid < 29) {
        const float* src; u16 *dh, *dl; int CIN = 64, COUT = 64, b0;
        if      (bid < 2)  { src = cv1w; dh = wh+WO_CV1;  dl = wl+WO_CV1;  CIN = 128; b0 = 0; }
        else if (bid < 3)  { src = m0a;  dh = wh+WO_M0A;  dl = wl+WO_M0A;  b0 = 2; }
        else if (bid < 12) { src = m0b;  dh = wh+WO_M0B;  dl = wl+WO_M0B;  b0 = 3; }
        else if (bid < 13) { src = m1a;  dh = wh+WO_M1A;  dl = wl+WO_M1A;  b0 = 12; }
        else if (bid < 22) { src = m1b;  dh = wh+WO_M1B;  dl = wl+WO_M1B;  b0 = 13; }
        else if (bid < 23) { src = cv3;  dh = wh+WO_CV3;  dl = wl+WO_CV3;  b0 = 22; }
        else if (bid < 25) { src = cv2p; dh = wh+WO_CV2P; dl = wl+WO_CV2P; CIN = 128; b0 = 23; }
        else               { src = cv4;  dh = wh+WO_CV4;  dl = wl+WO_CV4;  CIN = 128; COUT = 128; b0 = 25; }
        const int base = (bid - b0) * 4096;
        const int per = CIN * COUT;
        #pragma unroll 4
        for (int j = 0; j < 16; j++) {
            int e = base + tid + j * 256;
            int tap = e / per, r = e - tap * per;
            int ci = r / COUT, co = r - ci * COUT;
            float w = src[e];
            __half h = __float2half_rn(w);
            __half l = __float2half_rn(w - __half2float(h));
            int d = tap * per + co * CIN + ci;
            dh[d] = *(u16*)&h; dl[d] = *(u16*)&l;
        }
    } else if (bid == 29) {
        auto seg = [&](int off, const float* s, int C, int stride, int choff){
            for (int c = tid; c < C; c += 256) {
                float g = s[choff + c], b = s[stride + choff + c];
                float m = s[2*stride + choff + c], v = s[3*stride + choff + c];
                float sc = g * rsqrtf(v + 1e-3f);
                sb[off + c] = sc; sb[off + C + c] = b - m * sc;
            }
        };
        seg(SB_CV1,  c1bn, 64, 64, 0);
        seg(SB_M0A,  a0bn, 64, 64, 0);
        seg(SB_M0B,  b0bn, 64, 64, 0);
        seg(SB_M1A,  a1bn, 64, 64, 0);
        seg(SB_M1B,  b1bn, 64, 64, 0);
        seg(SB_CATA, catbn, 64, 128, 0);
        seg(SB_CATB, catbn, 64, 128, 64);
        seg(SB_CV4,       c4bn, 64, 128, 0);
        seg(SB_CV4 + 128, c4bn, 64, 128, 64);
    } else {
        int i = (bid - 30) * 256 + tid;
        if (i >= 16 * 644) return;
        int img = i / 644, r = i - img * 644;
        int y, x;
        if      (r < 162) { y = 0;   x = r; }
        else if (r < 324) { y = 161; x = r - 162; }
        else if (r < 484) { x = 0;   y = r - 324 + 1; }
        else              { x = 161; y = r - 484 + 1; }
        long long q = (((long long)img * 162 + y) * 162 + x) * 64;
        uint4 z = make_uint4(0,0,0,0);
        #pragma unroll
        for (int c = 0; c < 8; c++) { *(uint4*)(th + q + c*8) = z; *(uint4*)(tl + q + c*8) = z; }
    }
}

// ─── 1x1 conv GEMM (HMMA): persistent CTAs, pipelined A, W preloaded ───────
template<int CIN, int SRC, int OUTM, int ACT>
__global__ void __launch_bounds__(256, 2) g1x1(
    const float* __restrict__ xf,
    const u16* __restrict__ pah, const u16* __restrict__ pal,
    const u16* __restrict__ pbh, const u16* __restrict__ pbl,
    const u16* __restrict__ wh,  const u16* __restrict__ wl,
    const float* __restrict__ sb,
    u16* __restrict__ oh, u16* __restrict__ ol, float* __restrict__ of,
    int ntiles)
{
    constexpr int KB  = CIN / 64;
    constexpr int APL = 128 * STR * 2;   // 18432 per plane
    constexpr int WPL = 64 * STR * 2;    // 9216  per plane

    extern __shared__ char sm[];
    float* sbs  = (float*)sm;
    char* Wbase = sm + 512;                  // [kb][hi|lo]
    char* Abase = Wbase + KB * 2 * WPL;      // [buf][hi|lo]

    const int tid = threadIdx.x;
    const int cy  = blockIdx.y;
    const u16* whp = wh + cy * 64 * CIN;
    const u16* wlp = wl + cy * 64 * CIN;

    for (int c = tid; c < 128; c += 256) sbs[c] = sb[cy * 128 + c];

    const u32 WA = smem_u32(Wbase), AA = smem_u32(Abase);

    #pragma unroll
    for (int kb = 0; kb < KB; kb++)
        for (int i = tid; i < 512; i += 256) {
            int n = i >> 3, c8 = i & 7;
            u32 off = kb * 2 * WPL + (n * STR + c8 * 8) * 2;
            CPA16(WA + off,       whp + n * CIN + kb * 64 + c8 * 8);
            CPA16(WA + off + WPL, wlp + n * CIN + kb * 64 + c8 * 8);
        }

    auto stageA = [&](int t, int kb, int buf){
        long long p0 = (long long)t * 128;
        const u32 AH = AA + buf * 2 * APL;
        char* AB = Abase + buf * 2 * APL;
        for (int i = tid; i < 1024; i += 256) {
            int row = i >> 3, c8 = i & 7;
            u32 off = (row * STR + c8 * 8) * 2;
            if (SRC == 0) {
                const float* g = xf + (p0 + row) * CIN + kb * 64 + c8 * 8;
                float4 f1 = *(const float4*)g, f2 = *(const float4*)(g + 4);
                uint4 H, L;
                sp2(f1.x, f1.y, H.x, L.x); sp2(f1.z, f1.w, H.y, L.y);
                sp2(f2.x, f2.y, H.z, L.z); sp2(f2.z, f2.w, H.w, L.w);
                *(uint4*)(AB + off) = H; *(uint4*)(AB + APL + off) = L;
            } else if (SRC == 1) {
                CPA16(AH + off,       pah + (p0 + row) * CIN + kb * 64 + c8 * 8);
                CPA16(AH + APL + off, pal + (p0 + row) * CIN + kb * 64 + c8 * 8);
            } else {
                const u16* shp = kb ? pbh : pah;
                const u16* slp = kb ? pbl : pal;
                long long so = (p0 + row) * 64 + c8 * 8;
                CPA16(AH + off,       shp + so);
                CPA16(AH + APL + off, slp + so);
            }
        }
    };

    const int warp = tid >> 5, lane = tid & 31;
    const int arow  = 16 * warp + (lane & 7) + ((lane & 8) ? 8 : 0);
    const int akoff = (lane & 16) ? 8 : 0;
    const u32 aOff = (arow * STR + akoff) * 2;
    const int brow  = (lane & 7) + ((lane & 16) ? 8 : 0);
    const int bkoff = (lane & 8) ? 8 : 0;
    const u32 bOff = (brow * STR + bkoff) * 2;

    const int gr = lane >> 2, c2l = (lane & 3) * 2;
    const int coff = cy * 64;

    const int t0 = blockIdx.x;
    if (t0 < ntiles) stageA(t0, 0, 0);
    CPA_COMMIT();

    int buf = 0;
    float accF[8][4];
    u32 accH[8][2];
    u32 Ab[2][8], Bb[2][16];

    for (int t = t0; t < ntiles; t += gridDim.x) {
        #pragma unroll
        for (int n = 0; n < 8; n++) {
            #pragma unroll
            for (int j = 0; j < 4; j++) accF[n][j] = 0.f;
            accH[n][0] = 0u; accH[n][1] = 0u;
        }

        #pragma unroll
        for (int kb = 0; kb < KB; kb++) {
            int nt = t, nkb = kb + 1;
            if (nkb == KB) { nkb = 0; nt = t + gridDim.x; }
            const bool hn = (nt < ntiles);
            if (hn) stageA(nt, nkb, buf ^ 1);
            CPA_COMMIT();
            if (hn) { CPA_WAIT_G1(); } else { CPA_WAIT0(); }
            __syncthreads();

            const u32 aH = AA + buf * 2 * APL + aOff;
            const u32 aL = aH + APL;
            const u32 bH = WA + kb * 2 * WPL + bOff;
            const u32 bL = bH + WPL;

            gemm_block(accF, accH, aH, aL, bH, bL, Ab, Bb);

            if (kb == KB - 1) {
                #pragma unroll
                for (int rs = 0; rs < 2; rs++) {
                    int row = 16*warp + 8*rs + gr;
                    long long p = (long long)t * 128 + row;
                    long long q = 0;
                    if (OUTM == 0) q = p * 64;
                    else if (OUTM == 1) {
                        int pi = (int)p;
                        int img = pi / 25600, r = pi - img * 25600;
                        int y = r / 160, x = r - y * 160;
                        q = (((long long)img * 162 + y + 1) * 162 + (x + 1)) * 64;
                    }
                    #pragma unroll
                    for (int nb = 0; nb < 8; nb++) {
                        float2 hc = dec(accH[nb][rs]);
                        float v0 = sbs[8*nb + c2l]     * (accF[nb][2*rs]     + hc.x) + sbs[64 + 8*nb + c2l];
                        float v1 = sbs[8*nb + c2l + 1] * (accF[nb][2*rs + 1] + hc.y) + sbs[64 + 8*nb + c2l + 1];
                        if (ACT == 0) { v0 = hswish(v0); v1 = hswish(v1); }
                        else { v0 = v0 >= 0.f ? v0 : 0.1f*v0; v1 = v1 >= 0.f ? v1 : 0.1f*v1; }
                        if (OUTM == 2) {
                            *(float2*)(of + p * 128 + coff + 8*nb + c2l) = make_float2(v0, v1);
                        } else {
                            u32 H, L; sp2(v0, v1, H, L);
                            *(u32*)(oh + q + 8*nb + c2l) = H;
                            *(u32*)(ol + q + 8*nb + c2l) = L;
                        }
                    }
                }
            }
            __syncthreads();
            buf ^= 1;
        }
    }
}

// ─── 3x3 conv + BN + hswish + residual, pipelined taps (R8 structure) ──────
__global__ void __launch_bounds__(256, 2) c3x3(
    const u16* __restrict__ th, const u16* __restrict__ tl,
    const u16* __restrict__ wh, const u16* __restrict__ wl,
    const float* __restrict__ sb,
    u16* __restrict__ yh, u16* __restrict__ yl)
{
    constexpr int APL = 180 * STR * 2;   // 25920 per plane
    constexpr int WPL = 64 * STR * 2;    // 9216  per plane

    extern __shared__ char sm[];
    float* sbs = (float*)sm;
    char* Ah = sm + 512;
    char* Al = Ah + APL;
    char* Wb = Al + APL;                 // [buf][hi|lo]

    const int tid = threadIdx.x;
    const int blk = blockIdx.x;              // 16 imgs * 200 tiles (20x10)
    const int img = blk / 200, t = blk - img * 200;
    const int ty = t / 10, tx = t - ty * 10;
    const int y0 = ty * 8, x0 = tx * 16;

    for (int c = tid; c < 128; c += 256) sbs[c] = sb[c];

    const u32 AhA = smem_u32(Ah), AlA = smem_u32(Al), WbA = smem_u32(Wb);

    for (int i = tid; i < 1440; i += 256) {
        int hr = i >> 3, c8 = i & 7;
        int hy = hr / 18, hx = hr - hy * 18;
        long long s = (((long long)img * 162 + y0 + hy) * 162 + (x0 + hx)) * 64 + c8 * 8;
        u32 off = (hr * STR + c8 * 8) * 2;
        CPA16(AhA + off, th + s);
        CPA16(AlA + off, tl + s);
    }
    for (int i = tid; i < 512; i += 256) {
        int n = i >> 3, c8 = i & 7;
        u32 off = (n * STR + c8 * 8) * 2;
        CPA16(WbA + off,       wh + n*64 + c8*8);
        CPA16(WbA + WPL + off, wl + n*64 + c8*8);
    }
    CPA_WAIT();
    __syncthreads();

    const int warp = tid >> 5, lane = tid & 31;
    const int acol  = lane & 15;
    const int akoff = (lane & 16) ? 8 : 0;
    const int brow  = (lane & 7) + ((lane & 16) ? 8 : 0);
    const int bkoff = (lane & 8) ? 8 : 0;
    const u32 bOff = (brow * STR + bkoff) * 2;

    float accF[8][4];
    u32 accH[8][2];
    #pragma unroll
    for (int n = 0; n < 8; n++) {
        #pragma unroll
        for (int j = 0; j < 4; j++) accF[n][j] = 0.f;
        accH[n][0] = 0u; accH[n][1] = 0u;
    }

    u32 Ab[2][8], Bb[2][16];

    for (int tap = 0; tap < 9; tap++) {
        const int buf = tap & 1;
        if (tap < 8) {
            const u16* sh = wh + (tap+1)*4096;
            const u16* sl = wl + (tap+1)*4096;
            const u32 WA = WbA + (buf^1)*2*WPL;
            for (int i = tid; i < 512; i += 256) {
                int n = i >> 3, c8 = i & 7;
                u32 off = (n * STR + c8 * 8) * 2;
                CPA16(WA + off,       sh + n*64 + c8*8);
                CPA16(WA + WPL + off, sl + n*64 + c8*8);
            }
            CPA_COMMIT();
        }
        const int kh = tap / 3, kw = tap - kh * 3;
        const int hr = (warp + kh) * 18 + acol + kw;
        const u32 aH = AhA + (hr * STR + akoff) * 2;
        const u32 aL = AlA + (hr * STR + akoff) * 2;
        const u32 bH = WbA + buf*2*WPL + bOff;
        const u32 bL = bH + WPL;

        gemm_block(accF, accH, aH, aL, bH, bL, Ab, Bb);

        if (tap < 8) {
            CPA_WAIT0();
            __syncthreads();
        }
    }

    const int gr = lane >> 2, c2l = (lane & 3) * 2;
    #pragma unroll
    for (int rs = 0; rs < 2; rs++) {
        int xx = 8*rs + gr;
        long long q = ((long long)img * 25600 + (y0 + warp) * 160 + (x0 + xx)) * 64;
        #pragma unroll
        for (int nb = 0; nb < 8; nb++) {
            float2 yv0 = dec(*(const u32*)(yh + q + 8*nb + c2l));
            float2 yv1 = dec(*(const u32*)(yl + q + 8*nb + c2l));
            float2 hc  = dec(accH[nb][rs]);
            float v0 = sbs[8*nb + c2l]     * (accF[nb][2*rs]     + hc.x) + sbs[64 + 8*nb + c2l];
            float v1 = sbs[8*nb + c2l + 1] * (accF[nb][2*rs + 1] + hc.y) + sbs[64 + 8*nb + c2l + 1];
            v0 = hswish(v0) + yv0.x + yv1.x;
            v1 = hswish(v1) + yv0.y + yv1.y;
            u32 H, L; sp2(v0, v1, H, L);
            *(u32*)(yh + q + 8*nb + c2l) = H;
            *(u32*)(yl + q + 8*nb + c2l) = L;
        }
    }
}

// ─── host ──────────────────────────────────────────────────────────────────
extern "C" void kernel_launch(void* const* d_in, const int* in_sizes, int n_in,
                              void* d_out, int out_size)
{
    (void)in_sizes; (void)n_in; (void)out_size;
    const float* x         = (const float*)d_in[0];
    const float* cv1_w     = (const float*)d_in[1];
    const float* cv1_bn    = (const float*)d_in[2];
    const float* m0_cv1_w  = (const float*)d_in[3];
    const float* m0_cv1_bn = (const float*)d_in[4];
    const float* m0_cv2_w  = (const float*)d_in[5];
    const float* m0_cv2_bn = (const float*)d_in[6];
    const float* m1_cv1_w  = (const float*)d_in[7];
    const float* m1_cv1_bn = (const float*)d_in[8];
    const float* m1_cv2_w  = (const float*)d_in[9];
    const float* m1_cv2_bn = (const float*)d_in[10];
    const float* cv3_w     = (const float*)d_in[11];
    const float* cv2p_w    = (const float*)d_in[12];
    const float* bn_cat    = (const float*)d_in[13];
    const float* cv4_w     = (const float*)d_in[14];
    const float* cv4_bn    = (const float*)d_in[15];
    float* out = (float*)d_out;

    u16 *yh, *yl, *ah, *al, *bh, *bl, *th, *tl, *wh, *wl;
    float* sb;
    cudaGetSymbolAddress((void**)&yh, g_yh); cudaGetSymbolAddress((void**)&yl, g_yl);
    cudaGetSymbolAddress((void**)&ah, g_ah); cudaGetSymbolAddress((void**)&al, g_al);
    cudaGetSymbolAddress((void**)&bh, g_bh); cudaGetSymbolAddress((void**)&bl, g_bl);
    cudaGetSymbolAddress((void**)&th, g_th); cudaGetSymbolAddress((void**)&tl, g_tl);
    cudaGetSymbolAddress((void**)&wh, g_wh); cudaGetSymbolAddress((void**)&wl, g_wl);
    cudaGetSymbolAddress((void**)&sb, g_sb);

    constexpr int S1_64  = 512 + 1*2*9216 + 2*2*18432;     // 92672
    constexpr int S1_128 = 512 + 2*2*9216 + 2*2*18432;     // 111104
    constexpr int S3     = 512 + 2*25920 + 4*9216;         // 89216
    constexpr int NT = 3200;
    constexpr int GP = 304;

    cudaFuncSetAttribute(g1x1<128,0,0,0>, cudaFuncAttributeMaxDynamicSharedMemorySize, S1_128);
    cudaFuncSetAttribute(g1x1< 64,1,1,0>, cudaFuncAttributeMaxDynamicSharedMemorySize, S1_64);
    cudaFuncSetAttribute(g1x1< 64,1,0,1>, cudaFuncAttributeMaxDynamicSharedMemorySize, S1_64);
    cudaFuncSetAttribute(g1x1<128,0,0,1>, cudaFuncAttributeMaxDynamicSharedMemorySize, S1_128);
    cudaFuncSetAttribute(g1x1<128,2,2,0>, cudaFuncAttributeMaxDynamicSharedMemorySize, S1_128);
    cudaFuncSetAttribute(c3x3,            cudaFuncAttributeMaxDynamicSharedMemorySize, S3);

    prep_all<<<71, 256>>>(cv1_w, m0_cv1_w, m0_cv2_w, m1_cv1_w, m1_cv2_w,
                          cv3_w, cv2p_w, cv4_w,
                          cv1_bn, m0_cv1_bn, m0_cv2_bn, m1_cv1_bn, m1_cv2_bn,
                          bn_cat, cv4_bn, wh, wl, sb, th, tl);

    g1x1<128,0,0,0><<<GP,256,S1_128>>>(x, 0,0,0,0, wh+WO_CV1, wl+WO_CV1, sb+SB_CV1, yh, yl, 0, NT);
    g1x1<64,1,1,0><<<GP,256,S1_64>>>(0, yh,yl,0,0, wh+WO_M0A, wl+WO_M0A, sb+SB_M0A, th, tl, 0, NT);
    c3x3<<<3200,256,S3>>>(th, tl, wh+WO_M0B, wl+WO_M0B, sb+SB_M0B, yh, yl);
    g1x1<64,1,1,0><<<GP,256,S1_64>>>(0, yh,yl,0,0, wh+WO_M1A, wl+WO_M1A, sb+SB_M1A, th, tl, 0, NT);
    c3x3<<<3200,256,S3>>>(th, tl, wh+WO_M1B, wl+WO_M1B, sb+SB_M1B, yh, yl);
    g1x1<64,1,0,1><<<GP,256,S1_64>>>(0, yh,yl,0,0, wh+WO_CV3, wl+WO_CV3, sb+SB_CATA, ah, al, 0, NT);
    g1x1<128,0,0,1><<<GP,256,S1_128>>>(x, 0,0,0,0, wh+WO_CV2P, wl+WO_CV2P, sb+SB_CATB, bh, bl, 0, NT);
    g1x1<128,2,2,0><<<dim3(GP,2),256,S1_128>>>(0, ah,al, bh,bl, wh+WO_CV4, wl+WO_CV4, sb+SB_CV4, 0, 0, out, NT);
}